// round 9
// baseline (speedup 1.0000x reference)
#include <cuda_runtime.h>
#include <cuda_bf16.h>

// ---------------------------------------------------------------------------
// GAT-style sparse attention, CSR-fused formulation.
//   Chain A: bprep -> qkv_mma (mma.sync bf16 hi/lo ~ fp32)       [stream s1]
//   Chain B: hist -> scan_fused -> scatter                       [stream 0]
//   Join:    agg (fused softmax + aggregate, warp per node)      [stream 0]
// edge_index arrives as int32.  Plain sm_103 target: mma.sync/ldmatrix only.
// ---------------------------------------------------------------------------

#define IN_DIM 256
#define HD 32
#define NMAX 100000
#define EMAX 1600000
#define SCAN_BLK 1024

__device__ __align__(16) float g_Q[NMAX * HD];
__device__ __align__(16) float g_K[NMAX * HD];
__device__ __align__(16) float g_V[NMAX * HD];
__device__ int g_cnt[NMAX];       // zero at load; agg re-zeros for next call
__device__ int g_rowptr[NMAX];
__device__ int g_cursor[NMAX];
__device__ int g_sdst[EMAX];
__device__ int g_bsum[128];
__device__ int g_boff[128];
__device__ int g_ready1[128];     // zero at load; self-resetting per run
__device__ int g_ready2[128];
// Pre-built bf16 hi/lo of B = W^T: [4 chunks][96 rows][64 k] bf16 (uint pairs)
__device__ __align__(16) unsigned g_Bh[4 * 96 * 32];
__device__ __align__(16) unsigned g_Bl[4 * 96 * 32];

// ---------------------------------------------------------------------------
// helpers
// ---------------------------------------------------------------------------
__device__ __forceinline__ unsigned smem_u32(const void* p)
{
    unsigned a;
    asm("{ .reg .u64 t; cvta.to.shared.u64 t, %1; cvt.u32.u64 %0, t; }"
        : "=r"(a) : "l"(p));
    return a;
}
__device__ __forceinline__ unsigned short bf16h(float x)
{
    return __bfloat16_as_ushort(__float2bfloat16(x));
}
__device__ __forceinline__ float bf16f(unsigned short u)
{
    return __bfloat162float(__ushort_as_bfloat16(u));
}

__device__ __forceinline__ void ldsm_x4(unsigned r[4], unsigned addr)
{
    asm volatile("ldmatrix.sync.aligned.m8n8.x4.shared.b16 {%0,%1,%2,%3}, [%4];"
                 : "=r"(r[0]), "=r"(r[1]), "=r"(r[2]), "=r"(r[3]) : "r"(addr));
}
__device__ __forceinline__ void ldsm_x2(unsigned r[2], unsigned addr)
{
    asm volatile("ldmatrix.sync.aligned.m8n8.x2.shared.b16 {%0,%1}, [%2];"
                 : "=r"(r[0]), "=r"(r[1]) : "r"(addr));
}
__device__ __forceinline__ void mma_bf16(float c[4], const unsigned a[4],
                                         const unsigned b[2])
{
    asm volatile("mma.sync.aligned.m16n8k16.row.col.f32.bf16.bf16.f32 "
                 "{%0,%1,%2,%3}, {%4,%5,%6,%7}, {%8,%9}, {%0,%1,%2,%3};"
                 : "+f"(c[0]), "+f"(c[1]), "+f"(c[2]), "+f"(c[3])
                 : "r"(a[0]), "r"(a[1]), "r"(a[2]), "r"(a[3]),
                   "r"(b[0]), "r"(b[1]));
}

// ---------------------------------------------------------------------------
// B prep: bf16 hi/lo of W^T.  g_Bh[c][n][k] for k in [64c,64c+64).
// ---------------------------------------------------------------------------
__global__ void bprep_kernel(const float* __restrict__ Wq,
                             const float* __restrict__ Wk,
                             const float* __restrict__ Wv)
{
    for (int idx = threadIdx.x; idx < 12288; idx += blockDim.x) {
        int c   = idx / 3072;
        int rem = idx % 3072;
        int n   = rem / 32;
        int jp  = rem % 32;
        int k0  = c * 64 + 2 * jp;
        const float* Wm = (n < 32) ? Wq : (n < 64) ? Wk : Wv;
        float w0 = Wm[k0 * HD + (n & 31)];
        float w1 = Wm[(k0 + 1) * HD + (n & 31)];
        unsigned short h0 = bf16h(w0), h1 = bf16h(w1);
        unsigned short l0 = bf16h(w0 - bf16f(h0));
        unsigned short l1 = bf16h(w1 - bf16f(h1));
        g_Bh[idx] = (unsigned)h0 | ((unsigned)h1 << 16);
        g_Bl[idx] = (unsigned)l0 | ((unsigned)l1 << 16);
    }
}

// ---------------------------------------------------------------------------
// QKV GEMM via mma.sync bf16 hi/lo, software-pipelined X staging.
// ---------------------------------------------------------------------------
#define ASTRIDE 72
#define SM_AH 0
#define SM_AL 18432
#define SM_BH 36864
#define SM_BL 50688
#define QKV_SMEM 64512

__global__ void __launch_bounds__(256, 1)
qkv_mma_kernel(const float* __restrict__ X, int N)
{
    extern __shared__ char smem[];
    const unsigned sb = smem_u32(smem);
    const int tid  = threadIdx.x;
    const int wid  = tid >> 5;
    const int lane = tid & 31;
    const int n0   = blockIdx.x * 128;

    float acc[12][4];
    #pragma unroll
    for (int j = 0; j < 12; j++)
        #pragma unroll
        for (int i = 0; i < 4; i++) acc[j][i] = 0.f;

    const int a_row = (lane & 15);
    const int a_kh  = ((lane >> 4) & 1) * 8;
    const int b_row = (lane & 7);
    const int b_kh  = ((lane >> 3) & 1) * 8;

    float4 xv[8];
    #pragma unroll
    for (int ii = 0; ii < 8; ii++) {
        int q = tid + 256 * ii;
        int r = q >> 4, j4 = q & 15;
        int node = n0 + r;
        xv[ii] = (node < N)
            ? *(const float4*)&X[(size_t)node * IN_DIM + 4 * j4]
            : make_float4(0.f, 0.f, 0.f, 0.f);
    }

    for (int c = 0; c < 4; c++) {
        __syncthreads();

        #pragma unroll
        for (int ii = 0; ii < 8; ii++) {
            int q = tid + 256 * ii;
            int r = q >> 4, j4 = q & 15;
            float4 v = xv[ii];
            unsigned short hx = bf16h(v.x), hy = bf16h(v.y),
                           hz = bf16h(v.z), hw = bf16h(v.w);
            unsigned short lx = bf16h(v.x - bf16f(hx)), ly = bf16h(v.y - bf16f(hy)),
                           lz = bf16h(v.z - bf16f(hz)), lw = bf16h(v.w - bf16f(hw));
            unsigned byte = r * (ASTRIDE * 2) + 8 * j4;
            *(uint2*)(smem + SM_AH + byte) =
                make_uint2((unsigned)hx | ((unsigned)hy << 16),
                           (unsigned)hz | ((unsigned)hw << 16));
            *(uint2*)(smem + SM_AL + byte) =
                make_uint2((unsigned)lx | ((unsigned)ly << 16),
                           (unsigned)lz | ((unsigned)lw << 16));
        }

        #pragma unroll
        for (int i = tid, ii = 0; ii < 3; i += 256, ii++) {
            int n = i >> 3;
            int j = i & 7;
            unsigned byte = n * (ASTRIDE * 2) + 16 * j;
            *(uint4*)(smem + SM_BH + byte) = ((const uint4*)g_Bh)[c * 768 + i];
            *(uint4*)(smem + SM_BL + byte) = ((const uint4*)g_Bl)[c * 768 + i];
        }
        __syncthreads();

        if (c < 3) {
            #pragma unroll
            for (int ii = 0; ii < 8; ii++) {
                int q = tid + 256 * ii;
                int r = q >> 4, j4 = q & 15;
                int node = n0 + r;
                xv[ii] = (node < N)
                    ? *(const float4*)&X[(size_t)node * IN_DIM + (c + 1) * 64 + 4 * j4]
                    : make_float4(0.f, 0.f, 0.f, 0.f);
            }
        }

        #pragma unroll
        for (int ks = 0; ks < 4; ks++) {
            unsigned ah[4], al[4];
            {
                unsigned byte = (wid * 16 + a_row) * (ASTRIDE * 2)
                              + (ks * 16 + a_kh) * 2;
                ldsm_x4(ah, sb + SM_AH + byte);
                ldsm_x4(al, sb + SM_AL + byte);
            }
            #pragma unroll
            for (int j = 0; j < 12; j++) {
                unsigned bh[2], bl[2];
                unsigned byte = (j * 8 + b_row) * (ASTRIDE * 2)
                              + (ks * 16 + b_kh) * 2;
                ldsm_x2(bh, sb + SM_BH + byte);
                ldsm_x2(bl, sb + SM_BL + byte);
                mma_bf16(acc[j], ah, bh);
                mma_bf16(acc[j], ah, bl);
                mma_bf16(acc[j], al, bh);
            }
        }
    }

    const int g  = lane >> 2;
    const int tt = lane & 3;
    const int row_hi = n0 + wid * 16 + g;
    const int row_lo = row_hi + 8;
    #pragma unroll
    for (int j = 0; j < 12; j++) {
        float* dst = (j < 4) ? g_Q : (j < 8) ? g_K : g_V;
        int col = 8 * (j & 3) + 2 * tt;
        if (row_hi < N)
            *(float2*)&dst[(size_t)row_hi * HD + col] =
                make_float2(acc[j][0], acc[j][1]);
        if (row_lo < N)
            *(float2*)&dst[(size_t)row_lo * HD + col] =
                make_float2(acc[j][2], acc[j][3]);
    }
}

// ---------------------------------------------------------------------------
// CSR build
// ---------------------------------------------------------------------------
__global__ void hist_kernel(const int* __restrict__ ei, int E)
{
    int e = blockIdx.x * blockDim.x + threadIdx.x;
    if (e < E) atomicAdd(&g_cnt[ei[e]], 1);
}

// Single-kernel exclusive scan (StreamScan): all blocks resident in wave 1
// (98 blocks < 148 SMs), block 0 aggregates.  Flags self-reset each run.
__global__ void __launch_bounds__(SCAN_BLK)
scan_fused_kernel(int N, int nb)
{
    __shared__ int wsum[32];
    __shared__ int sh2[128];
    __shared__ int s_boff;

    const int t    = threadIdx.x;
    const int lane = t & 31;
    const int wid  = t >> 5;
    const int b    = blockIdx.x;
    const int i    = b * SCAN_BLK + t;

    int v = (i < N) ? g_cnt[i] : 0;
    int x = v;
    #pragma unroll
    for (int off = 1; off < 32; off <<= 1) {
        int y = __shfl_up_sync(0xffffffffu, x, off);
        if (lane >= off) x += y;
    }
    if (lane == 31) wsum[wid] = x;
    __syncthreads();
    if (wid == 0) {
        int s = wsum[lane];
        #pragma unroll
        for (int off = 1; off < 32; off <<= 1) {
            int y = __shfl_up_sync(0xffffffffu, s, off);
            if (lane >= off) s += y;
        }
        wsum[lane] = s;
    }
    __syncthreads();
    const int base = (wid > 0) ? wsum[wid - 1] : 0;
    const int excl = base + x - v;                 // exclusive within block

    // publish block total (release)
    if (t == SCAN_BLK - 1) {
        g_bsum[b] = base + x;
        __threadfence();
        atomicExch(&g_ready1[b], 1);
    }

    // block 0: gather totals, scan, publish offsets (release)
    if (b == 0) {
        int val = 0;
        if (t < 128 && t < nb) {
            while (atomicAdd(&g_ready1[t], 0) == 0) {}
            __threadfence();                       // acquire
            val = g_bsum[t];
        }
        if (t < 128) sh2[t] = val;
        __syncthreads();
        #pragma unroll
        for (int off = 1; off < 128; off <<= 1) {
            int y = (t < 128 && t >= off) ? sh2[t - off] : 0;
            __syncthreads();
            if (t < 128) sh2[t] += y;
            __syncthreads();
        }
        if (t < 128) {
            g_boff[t] = sh2[t] - val;              // exclusive block offsets
        }
        __threadfence();
        if (t < 128 && t < nb) {
            atomicExch(&g_ready2[t], 1);
            atomicExch(&g_ready1[t], 0);           // reset for next run
        }
    }

    // all blocks: consume own offset (acquire), then write rowptr/cursor
    if (t == 0) {
        while (atomicAdd(&g_ready2[b], 0) == 0) {}
        __threadfence();
        s_boff = g_boff[b];
        atomicExch(&g_ready2[b], 0);               // reset for next run
    }
    __syncthreads();
    if (i < N) {
        int rp = s_boff + excl;
        g_rowptr[i] = rp;
        g_cursor[i] = rp;
    }
}

__global__ void scatter_kernel(const int* __restrict__ ei, int E)
{
    int e = blockIdx.x * blockDim.x + threadIdx.x;
    if (e >= E) return;
    int s = ei[e];
    int d = ei[E + e];
    int pos = atomicAdd(&g_cursor[s], 1);
    g_sdst[pos] = d;
}

// ---------------------------------------------------------------------------
// Fused softmax + aggregate: one warp per node, 16 edges in flight
// (4 per 8-lane group).  Re-zeros g_cnt for next call.
// ---------------------------------------------------------------------------
__global__ void __launch_bounds__(256)
agg_kernel(float* __restrict__ out, int N)
{
    const int warp = (blockIdx.x * blockDim.x + threadIdx.x) >> 5;
    const int lane = threadIdx.x & 31;
    if (warp >= N) return;
    const int n   = warp;
    const int g   = lane >> 3;
    const int sub = lane & 7;

    const float4 q4 = *(const float4*)&g_Q[(size_t)n * HD + sub * 4];

    const int rs  = g_rowptr[n];
    const int cnt = g_cnt[n];
    const int nit = (cnt + 15) >> 4;

    float4 acc = make_float4(0.f, 0.f, 0.f, 0.f);
    float  sw  = 0.f;

    for (int it = 0; it < nit; it++) {
        bool  vm[4];
        int   dm[4];
        #pragma unroll
        for (int m = 0; m < 4; m++) {
            int jj = it * 16 + g + 4 * m;
            vm[m] = (jj < cnt);
            dm[m] = vm[m] ? g_sdst[rs + jj] : 0;
        }

        // issue all 8 gathers up front for max MLP
        float4 km[4], um[4];
        #pragma unroll
        for (int m = 0; m < 4; m++)
            km[m] = *(const float4*)&g_K[(size_t)dm[m] * HD + sub * 4];
        #pragma unroll
        for (int m = 0; m < 4; m++)
            um[m] = *(const float4*)&g_V[(size_t)dm[m] * HD + sub * 4];

        float pm[4];
        #pragma unroll
        for (int m = 0; m < 4; m++)
            pm[m] = q4.x * km[m].x + q4.y * km[m].y
                  + q4.z * km[m].z + q4.w * km[m].w;
        #pragma unroll
        for (int off = 1; off <= 4; off <<= 1)
            #pragma unroll
            for (int m = 0; m < 4; m++)
                pm[m] += __shfl_xor_sync(0xffffffffu, pm[m], off);

        #pragma unroll
        for (int m = 0; m < 4; m++) {
            float w = vm[m] ? __expf(pm[m] * 0.17677669529663687f) : 0.f;
            sw += w;
            acc.x += w * um[m].x;
            acc.y += w * um[m].y;
            acc.z += w * um[m].z;
            acc.w += w * um[m].w;
        }
    }

    #pragma unroll
    for (int off = 8; off <= 16; off <<= 1) {
        acc.x += __shfl_xor_sync(0xffffffffu, acc.x, off);
        acc.y += __shfl_xor_sync(0xffffffffu, acc.y, off);
        acc.z += __shfl_xor_sync(0xffffffffu, acc.z, off);
        acc.w += __shfl_xor_sync(0xffffffffu, acc.w, off);
        sw    += __shfl_xor_sync(0xffffffffu, sw,    off);
    }

    if (lane == 0) g_cnt[n] = 0;

    if (lane < 8) {
        float inv = (sw > 0.f) ? (1.f / sw) : 0.f;
        float4 o = make_float4(acc.x * inv, acc.y * inv, acc.z * inv, acc.w * inv);
        *(float4*)&out[(size_t)n * HD + sub * 4] = o;
    }
}

// ---------------------------------------------------------------------------
// Launch: fork-join across two streams.  6 launches; agg is 6th (profiled).
// ---------------------------------------------------------------------------
extern "C" void kernel_launch(void* const* d_in, const int* in_sizes, int n_in,
                              void* d_out, int out_size)
{
    const float* X  = (const float*)d_in[0];
    const int*   ei = (const int*)d_in[1];     // int32 edge indices
    const float* Wq = (const float*)d_in[2];
    const float* Wk = (const float*)d_in[3];
    const float* Wv = (const float*)d_in[4];
    float* out = (float*)d_out;

    const int N = in_sizes[0] / IN_DIM;
    const int E = in_sizes[1] / 2;
    const int nscan = (N + SCAN_BLK - 1) / SCAN_BLK;

    static cudaStream_t s1 = nullptr;
    static cudaEvent_t  evF = nullptr, evA = nullptr;
    if (!s1) {
        cudaFuncSetAttribute(qkv_mma_kernel,
                             cudaFuncAttributeMaxDynamicSharedMemorySize,
                             QKV_SMEM);
        cudaStreamCreateWithFlags(&s1, cudaStreamNonBlocking);
        cudaEventCreateWithFlags(&evF, cudaEventDisableTiming);
        cudaEventCreateWithFlags(&evA, cudaEventDisableTiming);
    }

    // Fork: chain A on s1
    cudaEventRecord(evF, 0);
    cudaStreamWaitEvent(s1, evF, 0);
    bprep_kernel<<<1, 256, 0, s1>>>(Wq, Wk, Wv);                    // 1
    qkv_mma_kernel<<<(N + 127) / 128, 256, QKV_SMEM, s1>>>(X, N);   // 2
    cudaEventRecord(evA, s1);

    // Chain B on stream 0
    hist_kernel<<<(E + 255) / 256, 256>>>(ei, E);                   // 3
    scan_fused_kernel<<<nscan, SCAN_BLK>>>(N, nscan);               // 4
    scatter_kernel<<<(E + 255) / 256, 256>>>(ei, E);                // 5

    // Join + aggregate
    cudaStreamWaitEvent(0, evA, 0);
    agg_kernel<<<(N * 32 + 255) / 256, 256>>>(out, N);              // 6 <- profiled
}

// round 10
// speedup vs baseline: 1.1394x; 1.1394x over previous
#include <cuda_runtime.h>
#include <cuda_bf16.h>

// ---------------------------------------------------------------------------
// GAT-style sparse attention, CSR-fused formulation.  (R8 structure + agg
// index pipeline + vectorized hist/scatter.)
//   Chain A: bprep -> qkv_mma (mma.sync bf16 hi/lo ~ fp32)       [stream s1]
//   Chain B: hist -> scan1 -> scan2 -> scan3 -> scatter          [stream 0]
//   Join:    agg (fused softmax + aggregate, warp per node)      [stream 0]
// edge_index arrives as int32.  Plain sm_103 target: mma.sync/ldmatrix only.
// ---------------------------------------------------------------------------

#define IN_DIM 256
#define HD 32
#define NMAX 100000
#define EMAX 1600000
#define SCAN_BLK 1024

__device__ __align__(16) float g_Q[NMAX * HD];
__device__ __align__(16) float g_K[NMAX * HD];
__device__ __align__(16) float g_V[NMAX * HD];
__device__ int g_cnt[NMAX];       // zero at load; agg re-zeros for next call
__device__ int g_rowptr[NMAX];
__device__ int g_cursor[NMAX];
__device__ int g_sdst[EMAX];
__device__ int g_bsum[128];
// Pre-built bf16 hi/lo of B = W^T: [4 chunks][96 rows][64 k] bf16 (uint pairs)
__device__ __align__(16) unsigned g_Bh[4 * 96 * 32];
__device__ __align__(16) unsigned g_Bl[4 * 96 * 32];

// ---------------------------------------------------------------------------
// helpers
// ---------------------------------------------------------------------------
__device__ __forceinline__ unsigned smem_u32(const void* p)
{
    unsigned a;
    asm("{ .reg .u64 t; cvta.to.shared.u64 t, %1; cvt.u32.u64 %0, t; }"
        : "=r"(a) : "l"(p));
    return a;
}
__device__ __forceinline__ unsigned short bf16h(float x)
{
    return __bfloat16_as_ushort(__float2bfloat16(x));
}
__device__ __forceinline__ float bf16f(unsigned short u)
{
    return __bfloat162float(__ushort_as_bfloat16(u));
}

__device__ __forceinline__ void ldsm_x4(unsigned r[4], unsigned addr)
{
    asm volatile("ldmatrix.sync.aligned.m8n8.x4.shared.b16 {%0,%1,%2,%3}, [%4];"
                 : "=r"(r[0]), "=r"(r[1]), "=r"(r[2]), "=r"(r[3]) : "r"(addr));
}
__device__ __forceinline__ void ldsm_x2(unsigned r[2], unsigned addr)
{
    asm volatile("ldmatrix.sync.aligned.m8n8.x2.shared.b16 {%0,%1}, [%2];"
                 : "=r"(r[0]), "=r"(r[1]) : "r"(addr));
}
__device__ __forceinline__ void mma_bf16(float c[4], const unsigned a[4],
                                         const unsigned b[2])
{
    asm volatile("mma.sync.aligned.m16n8k16.row.col.f32.bf16.bf16.f32 "
                 "{%0,%1,%2,%3}, {%4,%5,%6,%7}, {%8,%9}, {%0,%1,%2,%3};"
                 : "+f"(c[0]), "+f"(c[1]), "+f"(c[2]), "+f"(c[3])
                 : "r"(a[0]), "r"(a[1]), "r"(a[2]), "r"(a[3]),
                   "r"(b[0]), "r"(b[1]));
}

// ---------------------------------------------------------------------------
// B prep: bf16 hi/lo of W^T.  g_Bh[c][n][k] for k in [64c,64c+64).
// ---------------------------------------------------------------------------
__global__ void bprep_kernel(const float* __restrict__ Wq,
                             const float* __restrict__ Wk,
                             const float* __restrict__ Wv)
{
    for (int idx = threadIdx.x; idx < 12288; idx += blockDim.x) {
        int c   = idx / 3072;
        int rem = idx % 3072;
        int n   = rem / 32;
        int jp  = rem % 32;
        int k0  = c * 64 + 2 * jp;
        const float* Wm = (n < 32) ? Wq : (n < 64) ? Wk : Wv;
        float w0 = Wm[k0 * HD + (n & 31)];
        float w1 = Wm[(k0 + 1) * HD + (n & 31)];
        unsigned short h0 = bf16h(w0), h1 = bf16h(w1);
        unsigned short l0 = bf16h(w0 - bf16f(h0));
        unsigned short l1 = bf16h(w1 - bf16f(h1));
        g_Bh[idx] = (unsigned)h0 | ((unsigned)h1 << 16);
        g_Bl[idx] = (unsigned)l0 | ((unsigned)l1 << 16);
    }
}

// ---------------------------------------------------------------------------
// QKV GEMM via mma.sync bf16 hi/lo, software-pipelined X staging.
// ---------------------------------------------------------------------------
#define ASTRIDE 72
#define SM_AH 0
#define SM_AL 18432
#define SM_BH 36864
#define SM_BL 50688
#define QKV_SMEM 64512

__global__ void __launch_bounds__(256, 1)
qkv_mma_kernel(const float* __restrict__ X, int N)
{
    extern __shared__ char smem[];
    const unsigned sb = smem_u32(smem);
    const int tid  = threadIdx.x;
    const int wid  = tid >> 5;
    const int lane = tid & 31;
    const int n0   = blockIdx.x * 128;

    float acc[12][4];
    #pragma unroll
    for (int j = 0; j < 12; j++)
        #pragma unroll
        for (int i = 0; i < 4; i++) acc[j][i] = 0.f;

    const int a_row = (lane & 15);
    const int a_kh  = ((lane >> 4) & 1) * 8;
    const int b_row = (lane & 7);
    const int b_kh  = ((lane >> 3) & 1) * 8;

    float4 xv[8];
    #pragma unroll
    for (int ii = 0; ii < 8; ii++) {
        int q = tid + 256 * ii;
        int r = q >> 4, j4 = q & 15;
        int node = n0 + r;
        xv[ii] = (node < N)
            ? *(const float4*)&X[(size_t)node * IN_DIM + 4 * j4]
            : make_float4(0.f, 0.f, 0.f, 0.f);
    }

    for (int c = 0; c < 4; c++) {
        __syncthreads();

        #pragma unroll
        for (int ii = 0; ii < 8; ii++) {
            int q = tid + 256 * ii;
            int r = q >> 4, j4 = q & 15;
            float4 v = xv[ii];
            unsigned short hx = bf16h(v.x), hy = bf16h(v.y),
                           hz = bf16h(v.z), hw = bf16h(v.w);
            unsigned short lx = bf16h(v.x - bf16f(hx)), ly = bf16h(v.y - bf16f(hy)),
                           lz = bf16h(v.z - bf16f(hz)), lw = bf16h(v.w - bf16f(hw));
            unsigned byte = r * (ASTRIDE * 2) + 8 * j4;
            *(uint2*)(smem + SM_AH + byte) =
                make_uint2((unsigned)hx | ((unsigned)hy << 16),
                           (unsigned)hz | ((unsigned)hw << 16));
            *(uint2*)(smem + SM_AL + byte) =
                make_uint2((unsigned)lx | ((unsigned)ly << 16),
                           (unsigned)lz | ((unsigned)lw << 16));
        }

        #pragma unroll
        for (int i = tid, ii = 0; ii < 3; i += 256, ii++) {
            int n = i >> 3;
            int j = i & 7;
            unsigned byte = n * (ASTRIDE * 2) + 16 * j;
            *(uint4*)(smem + SM_BH + byte) = ((const uint4*)g_Bh)[c * 768 + i];
            *(uint4*)(smem + SM_BL + byte) = ((const uint4*)g_Bl)[c * 768 + i];
        }
        __syncthreads();

        if (c < 3) {
            #pragma unroll
            for (int ii = 0; ii < 8; ii++) {
                int q = tid + 256 * ii;
                int r = q >> 4, j4 = q & 15;
                int node = n0 + r;
                xv[ii] = (node < N)
                    ? *(const float4*)&X[(size_t)node * IN_DIM + (c + 1) * 64 + 4 * j4]
                    : make_float4(0.f, 0.f, 0.f, 0.f);
            }
        }

        #pragma unroll
        for (int ks = 0; ks < 4; ks++) {
            unsigned ah[4], al[4];
            {
                unsigned byte = (wid * 16 + a_row) * (ASTRIDE * 2)
                              + (ks * 16 + a_kh) * 2;
                ldsm_x4(ah, sb + SM_AH + byte);
                ldsm_x4(al, sb + SM_AL + byte);
            }
            #pragma unroll
            for (int j = 0; j < 12; j++) {
                unsigned bh[2], bl[2];
                unsigned byte = (j * 8 + b_row) * (ASTRIDE * 2)
                              + (ks * 16 + b_kh) * 2;
                ldsm_x2(bh, sb + SM_BH + byte);
                ldsm_x2(bl, sb + SM_BL + byte);
                mma_bf16(acc[j], ah, bh);
                mma_bf16(acc[j], ah, bl);
                mma_bf16(acc[j], al, bh);
            }
        }
    }

    const int g  = lane >> 2;
    const int tt = lane & 3;
    const int row_hi = n0 + wid * 16 + g;
    const int row_lo = row_hi + 8;
    #pragma unroll
    for (int j = 0; j < 12; j++) {
        float* dst = (j < 4) ? g_Q : (j < 8) ? g_K : g_V;
        int col = 8 * (j & 3) + 2 * tt;
        if (row_hi < N)
            *(float2*)&dst[(size_t)row_hi * HD + col] =
                make_float2(acc[j][0], acc[j][1]);
        if (row_lo < N)
            *(float2*)&dst[(size_t)row_lo * HD + col] =
                make_float2(acc[j][2], acc[j][3]);
    }
}

// ---------------------------------------------------------------------------
// CSR build: histogram (int4), scan (warp-shuffle), scatter (int4)
// ---------------------------------------------------------------------------
__global__ void hist_kernel(const int* __restrict__ ei, int E)
{
    int b = (blockIdx.x * blockDim.x + threadIdx.x) * 4;
    if (b + 3 < E) {
        int4 s = *(const int4*)&ei[b];
        atomicAdd(&g_cnt[s.x], 1);
        atomicAdd(&g_cnt[s.y], 1);
        atomicAdd(&g_cnt[s.z], 1);
        atomicAdd(&g_cnt[s.w], 1);
    } else {
        for (int e = b; e < E; e++) atomicAdd(&g_cnt[ei[e]], 1);
    }
}

__global__ void scan1_kernel(int N)
{
    __shared__ int wsum[32];
    const int t    = threadIdx.x;
    const int lane = t & 31;
    const int wid  = t >> 5;
    const int i    = blockIdx.x * SCAN_BLK + t;

    int v = (i < N) ? g_cnt[i] : 0;
    int x = v;
    #pragma unroll
    for (int off = 1; off < 32; off <<= 1) {
        int y = __shfl_up_sync(0xffffffffu, x, off);
        if (lane >= off) x += y;
    }
    if (lane == 31) wsum[wid] = x;
    __syncthreads();
    if (wid == 0) {
        int s = wsum[lane];
        #pragma unroll
        for (int off = 1; off < 32; off <<= 1) {
            int y = __shfl_up_sync(0xffffffffu, s, off);
            if (lane >= off) s += y;
        }
        wsum[lane] = s;
    }
    __syncthreads();
    int base = (wid > 0) ? wsum[wid - 1] : 0;
    if (i < N) g_rowptr[i] = base + x - v;
    if (t == SCAN_BLK - 1) g_bsum[blockIdx.x] = base + x;
}

__global__ void scan2_kernel(int nb)
{
    __shared__ int sh[128];
    const int t = threadIdx.x;
    int v = (t < nb) ? g_bsum[t] : 0;
    sh[t] = v;
    __syncthreads();
    #pragma unroll
    for (int off = 1; off < 128; off <<= 1) {
        int x = (t >= off) ? sh[t - off] : 0;
        __syncthreads();
        sh[t] += x;
        __syncthreads();
    }
    if (t < nb) g_bsum[t] = sh[t] - v;
}

__global__ void scan3_kernel(int N)
{
    int i = blockIdx.x * blockDim.x + threadIdx.x;
    if (i < N) {
        int rp = g_rowptr[i] + g_bsum[i >> 10];
        g_rowptr[i] = rp;
        g_cursor[i] = rp;
    }
}

__global__ void scatter_kernel(const int* __restrict__ ei, int E)
{
    int b = (blockIdx.x * blockDim.x + threadIdx.x) * 4;
    if (b + 3 < E) {
        int4 s = *(const int4*)&ei[b];
        int4 d = *(const int4*)&ei[E + b];
        g_sdst[atomicAdd(&g_cursor[s.x], 1)] = d.x;
        g_sdst[atomicAdd(&g_cursor[s.y], 1)] = d.y;
        g_sdst[atomicAdd(&g_cursor[s.z], 1)] = d.z;
        g_sdst[atomicAdd(&g_cursor[s.w], 1)] = d.w;
    } else {
        for (int e = b; e < E; e++) {
            int s = ei[e];
            int d = ei[E + e];
            g_sdst[atomicAdd(&g_cursor[s], 1)] = d;
        }
    }
}

// ---------------------------------------------------------------------------
// Fused softmax + aggregate: one warp per node, 8 edges in flight, with
// next-iteration index prefetch.  Re-zeros g_cnt for next call.
// ---------------------------------------------------------------------------
__global__ void __launch_bounds__(256)
agg_kernel(float* __restrict__ out, int N)
{
    const int warp = (blockIdx.x * blockDim.x + threadIdx.x) >> 5;
    const int lane = threadIdx.x & 31;
    if (warp >= N) return;
    const int n   = warp;
    const int g   = lane >> 3;
    const int sub = lane & 7;

    const float4 q4 = *(const float4*)&g_Q[(size_t)n * HD + sub * 4];

    const int rs  = g_rowptr[n];
    const int cnt = g_cnt[n];
    const int nit = (cnt + 7) >> 3;

    float4 acc = make_float4(0.f, 0.f, 0.f, 0.f);
    float  sw  = 0.f;

    // Pre-load iteration 0's indices
    bool v0 = (g < cnt);
    bool v1 = (g + 4 < cnt);
    int  d0 = v0 ? g_sdst[rs + g] : 0;
    int  d1 = v1 ? g_sdst[rs + g + 4] : 0;

    for (int it = 0; it < nit; it++) {
        // Issue all 4 gathers for this iteration up front
        const float4 k0 = *(const float4*)&g_K[(size_t)d0 * HD + sub * 4];
        const float4 k1 = *(const float4*)&g_K[(size_t)d1 * HD + sub * 4];
        const float4 u0 = *(const float4*)&g_V[(size_t)d0 * HD + sub * 4];
        const float4 u1 = *(const float4*)&g_V[(size_t)d1 * HD + sub * 4];

        // Prefetch next iteration's indices (overlaps gather latency)
        bool nv0 = false, nv1 = false;
        int  nd0 = 0, nd1 = 0;
        if (it + 1 < nit) {
            int jj = (it + 1) * 8 + g;
            nv0 = (jj < cnt);
            nv1 = (jj + 4 < cnt);
            nd0 = nv0 ? g_sdst[rs + jj] : 0;
            nd1 = nv1 ? g_sdst[rs + jj + 4] : 0;
        }

        float p0 = q4.x * k0.x + q4.y * k0.y + q4.z * k0.z + q4.w * k0.w;
        float p1 = q4.x * k1.x + q4.y * k1.y + q4.z * k1.z + q4.w * k1.w;
        p0 += __shfl_xor_sync(0xffffffffu, p0, 1);
        p1 += __shfl_xor_sync(0xffffffffu, p1, 1);
        p0 += __shfl_xor_sync(0xffffffffu, p0, 2);
        p1 += __shfl_xor_sync(0xffffffffu, p1, 2);
        p0 += __shfl_xor_sync(0xffffffffu, p0, 4);
        p1 += __shfl_xor_sync(0xffffffffu, p1, 4);

        float w0 = v0 ? __expf(p0 * 0.17677669529663687f) : 0.f;
        float w1 = v1 ? __expf(p1 * 0.17677669529663687f) : 0.f;
        sw += w0 + w1;

        acc.x += w0 * u0.x + w1 * u1.x;
        acc.y += w0 * u0.y + w1 * u1.y;
        acc.z += w0 * u0.z + w1 * u1.z;
        acc.w += w0 * u0.w + w1 * u1.w;

        v0 = nv0; v1 = nv1; d0 = nd0; d1 = nd1;
    }

    #pragma unroll
    for (int off = 8; off <= 16; off <<= 1) {
        acc.x += __shfl_xor_sync(0xffffffffu, acc.x, off);
        acc.y += __shfl_xor_sync(0xffffffffu, acc.y, off);
        acc.z += __shfl_xor_sync(0xffffffffu, acc.z, off);
        acc.w += __shfl_xor_sync(0xffffffffu, acc.w, off);
        sw    += __shfl_xor_sync(0xffffffffu, sw,    off);
    }

    if (lane == 0) g_cnt[n] = 0;

    if (lane < 8) {
        float inv = (sw > 0.f) ? (1.f / sw) : 0.f;
        float4 o = make_float4(acc.x * inv, acc.y * inv, acc.z * inv, acc.w * inv);
        *(float4*)&out[(size_t)n * HD + sub * 4] = o;
    }
}

// ---------------------------------------------------------------------------
// Launch: fork-join across two streams (capture-safe event pattern).
// ---------------------------------------------------------------------------
extern "C" void kernel_launch(void* const* d_in, const int* in_sizes, int n_in,
                              void* d_out, int out_size)
{
    const float* X  = (const float*)d_in[0];
    const int*   ei = (const int*)d_in[1];     // int32 edge indices
    const float* Wq = (const float*)d_in[2];
    const float* Wk = (const float*)d_in[3];
    const float* Wv = (const float*)d_in[4];
    float* out = (float*)d_out;

    const int N = in_sizes[0] / IN_DIM;
    const int E = in_sizes[1] / 2;
    const int nscan = (N + SCAN_BLK - 1) / SCAN_BLK;

    static cudaStream_t s1 = nullptr;
    static cudaEvent_t  evF = nullptr, evA = nullptr;
    if (!s1) {
        cudaFuncSetAttribute(qkv_mma_kernel,
                             cudaFuncAttributeMaxDynamicSharedMemorySize,
                             QKV_SMEM);
        cudaStreamCreateWithFlags(&s1, cudaStreamNonBlocking);
        cudaEventCreateWithFlags(&evF, cudaEventDisableTiming);
        cudaEventCreateWithFlags(&evA, cudaEventDisableTiming);
    }

    // Fork: chain A on s1
    cudaEventRecord(evF, 0);
    cudaStreamWaitEvent(s1, evF, 0);
    bprep_kernel<<<1, 256, 0, s1>>>(Wq, Wk, Wv);
    qkv_mma_kernel<<<(N + 127) / 128, 256, QKV_SMEM, s1>>>(X, N);
    cudaEventRecord(evA, s1);

    // Chain B on stream 0
    hist_kernel<<<(E / 4 + 255) / 256, 256>>>(ei, E);
    scan1_kernel<<<nscan, SCAN_BLK>>>(N);
    scan2_kernel<<<1, 128>>>(nscan);
    scan3_kernel<<<(N + 255) / 256, 256>>>(N);
    scatter_kernel<<<(E / 4 + 255) / 256, 256>>>(ei, E);

    // Join + aggregate
    cudaStreamWaitEvent(0, evA, 0);
    agg_kernel<<<(N * 32 + 255) / 256, 256>>>(out, N);
}

// round 11
// speedup vs baseline: 1.1678x; 1.0249x over previous
#include <cuda_runtime.h>
#include <cuda_bf16.h>

// ---------------------------------------------------------------------------
// GAT-style sparse attention, CSR-fused formulation.  4 launches:
//   csr (hist+scan, grid-barrier)  [s0]   qkv (inline W-prep)  [s1]
//   scatter                        [s0]   agg (join)           [s0, profiled]
// edge_index arrives as int32.  Plain sm_103 target: mma.sync/ldmatrix only.
// ---------------------------------------------------------------------------

#define IN_DIM 256
#define HD 32
#define NMAX 100000
#define EMAX 1600000
#define SCAN_BLK 1024

__device__ __align__(16) float g_Q[NMAX * HD];
__device__ __align__(16) float g_KV[NMAX * 64];   // per node: K[0:32) | V[32:64)
__device__ int g_cnt[NMAX];       // zero at load; agg re-zeros for next call
__device__ int g_rowptr[NMAX];
__device__ int g_cursor[NMAX];
__device__ int g_sdst[EMAX];
__device__ int g_bsum[128];
// csr_kernel sync state (all zero at load; self-resetting each run)
__device__ int g_bar1, g_rel1, g_done1;
__device__ int g_ready[128];

// ---------------------------------------------------------------------------
// helpers
// ---------------------------------------------------------------------------
__device__ __forceinline__ unsigned smem_u32(const void* p)
{
    unsigned a;
    asm("{ .reg .u64 t; cvta.to.shared.u64 t, %1; cvt.u32.u64 %0, t; }"
        : "=r"(a) : "l"(p));
    return a;
}
__device__ __forceinline__ unsigned short bf16h(float x)
{
    return __bfloat16_as_ushort(__float2bfloat16(x));
}
__device__ __forceinline__ float bf16f(unsigned short u)
{
    return __bfloat162float(__ushort_as_bfloat16(u));
}

__device__ __forceinline__ void ldsm_x4(unsigned r[4], unsigned addr)
{
    asm volatile("ldmatrix.sync.aligned.m8n8.x4.shared.b16 {%0,%1,%2,%3}, [%4];"
                 : "=r"(r[0]), "=r"(r[1]), "=r"(r[2]), "=r"(r[3]) : "r"(addr));
}
__device__ __forceinline__ void ldsm_x2(unsigned r[2], unsigned addr)
{
    asm volatile("ldmatrix.sync.aligned.m8n8.x2.shared.b16 {%0,%1}, [%2];"
                 : "=r"(r[0]), "=r"(r[1]) : "r"(addr));
}
__device__ __forceinline__ void mma_bf16(float c[4], const unsigned a[4],
                                         const unsigned b[2])
{
    asm volatile("mma.sync.aligned.m16n8k16.row.col.f32.bf16.bf16.f32 "
                 "{%0,%1,%2,%3}, {%4,%5,%6,%7}, {%8,%9}, {%0,%1,%2,%3};"
                 : "+f"(c[0]), "+f"(c[1]), "+f"(c[2]), "+f"(c[3])
                 : "r"(a[0]), "r"(a[1]), "r"(a[2]), "r"(a[3]),
                   "r"(b[0]), "r"(b[1]));
}

// ---------------------------------------------------------------------------
// QKV GEMM via mma.sync bf16 hi/lo, software-pipelined X staging,
// per-chunk B built inline from W (hi/lo bf16 into padded smem).
// ---------------------------------------------------------------------------
#define ASTRIDE 72
#define SM_AH 0
#define SM_AL 18432
#define SM_BH 36864
#define SM_BL 50688
#define QKV_SMEM 64512

__global__ void __launch_bounds__(256, 1)
qkv_mma_kernel(const float* __restrict__ X,
               const float* __restrict__ Wq,
               const float* __restrict__ Wk,
               const float* __restrict__ Wv,
               int N)
{
    extern __shared__ char smem[];
    const unsigned sb = smem_u32(smem);
    const int tid  = threadIdx.x;
    const int wid  = tid >> 5;
    const int lane = tid & 31;
    const int n0   = blockIdx.x * 128;

    float acc[12][4];
    #pragma unroll
    for (int j = 0; j < 12; j++)
        #pragma unroll
        for (int i = 0; i < 4; i++) acc[j][i] = 0.f;

    const int a_row = (lane & 15);
    const int a_kh  = ((lane >> 4) & 1) * 8;
    const int b_row = (lane & 7);
    const int b_kh  = ((lane >> 3) & 1) * 8;

    float4 xv[8];
    #pragma unroll
    for (int ii = 0; ii < 8; ii++) {
        int q = tid + 256 * ii;
        int r = q >> 4, j4 = q & 15;
        int node = n0 + r;
        xv[ii] = (node < N)
            ? *(const float4*)&X[(size_t)node * IN_DIM + 4 * j4]
            : make_float4(0.f, 0.f, 0.f, 0.f);
    }

    for (int c = 0; c < 4; c++) {
        __syncthreads();

        // Stage A chunk c (hi/lo bf16) from prefetched registers
        #pragma unroll
        for (int ii = 0; ii < 8; ii++) {
            int q = tid + 256 * ii;
            int r = q >> 4, j4 = q & 15;
            float4 v = xv[ii];
            unsigned short hx = bf16h(v.x), hy = bf16h(v.y),
                           hz = bf16h(v.z), hw = bf16h(v.w);
            unsigned short lx = bf16h(v.x - bf16f(hx)), ly = bf16h(v.y - bf16f(hy)),
                           lz = bf16h(v.z - bf16f(hz)), lw = bf16h(v.w - bf16f(hw));
            unsigned byte = r * (ASTRIDE * 2) + 8 * j4;
            *(uint2*)(smem + SM_AH + byte) =
                make_uint2((unsigned)hx | ((unsigned)hy << 16),
                           (unsigned)hz | ((unsigned)hw << 16));
            *(uint2*)(smem + SM_AL + byte) =
                make_uint2((unsigned)lx | ((unsigned)ly << 16),
                           (unsigned)lz | ((unsigned)lw << 16));
        }

        // Build B chunk c inline from W: 3072 bf16-pairs (96 rows x 32 pairs)
        #pragma unroll
        for (int ii = 0; ii < 12; ii++) {
            int i  = tid + 256 * ii;          // 0..3071
            int n  = i % 96;
            int jp = i / 96;
            int k0 = c * 64 + 2 * jp;
            const float* Wm = (n < 32) ? Wq : (n < 64) ? Wk : Wv;
            float w0 = Wm[k0 * HD + (n & 31)];
            float w1 = Wm[(k0 + 1) * HD + (n & 31)];
            unsigned short h0 = bf16h(w0), h1 = bf16h(w1);
            unsigned short l0 = bf16h(w0 - bf16f(h0));
            unsigned short l1 = bf16h(w1 - bf16f(h1));
            unsigned byte = n * (ASTRIDE * 2) + 4 * jp;
            *(unsigned*)(smem + SM_BH + byte) = (unsigned)h0 | ((unsigned)h1 << 16);
            *(unsigned*)(smem + SM_BL + byte) = (unsigned)l0 | ((unsigned)l1 << 16);
        }
        __syncthreads();

        // Prefetch next chunk's X into registers (hidden under MMA compute)
        if (c < 3) {
            #pragma unroll
            for (int ii = 0; ii < 8; ii++) {
                int q = tid + 256 * ii;
                int r = q >> 4, j4 = q & 15;
                int node = n0 + r;
                xv[ii] = (node < N)
                    ? *(const float4*)&X[(size_t)node * IN_DIM + (c + 1) * 64 + 4 * j4]
                    : make_float4(0.f, 0.f, 0.f, 0.f);
            }
        }

        #pragma unroll
        for (int ks = 0; ks < 4; ks++) {
            unsigned ah[4], al[4];
            {
                unsigned byte = (wid * 16 + a_row) * (ASTRIDE * 2)
                              + (ks * 16 + a_kh) * 2;
                ldsm_x4(ah, sb + SM_AH + byte);
                ldsm_x4(al, sb + SM_AL + byte);
            }
            #pragma unroll
            for (int j = 0; j < 12; j++) {
                unsigned bh[2], bl[2];
                unsigned byte = (j * 8 + b_row) * (ASTRIDE * 2)
                              + (ks * 16 + b_kh) * 2;
                ldsm_x2(bh, sb + SM_BH + byte);
                ldsm_x2(bl, sb + SM_BL + byte);
                mma_bf16(acc[j], ah, bh);
                mma_bf16(acc[j], ah, bl);
                mma_bf16(acc[j], al, bh);
            }
        }
    }

    // Epilogue: Q separate; K/V interleaved per node (64-float row)
    const int g  = lane >> 2;
    const int tt = lane & 3;
    const int row_hi = n0 + wid * 16 + g;
    const int row_lo = row_hi + 8;
    #pragma unroll
    for (int j = 0; j < 12; j++) {
        int col = 8 * (j & 3) + 2 * tt;
        float* p_hi;
        float* p_lo;
        if (j < 4) {
            p_hi = &g_Q[(size_t)row_hi * HD + col];
            p_lo = &g_Q[(size_t)row_lo * HD + col];
        } else if (j < 8) {
            p_hi = &g_KV[(size_t)row_hi * 64 + col];
            p_lo = &g_KV[(size_t)row_lo * 64 + col];
        } else {
            p_hi = &g_KV[(size_t)row_hi * 64 + 32 + col];
            p_lo = &g_KV[(size_t)row_lo * 64 + 32 + col];
        }
        if (row_hi < N) *(float2*)p_hi = make_float2(acc[j][0], acc[j][1]);
        if (row_lo < N) *(float2*)p_lo = make_float2(acc[j][2], acc[j][3]);
    }
}

// ---------------------------------------------------------------------------
// CSR hist + scan in ONE kernel.  nb blocks (nb <= 128, all resident),
// counter grid-barrier between phases, flag-gathered block offsets.
// All sync state self-resets for graph replay determinism.
// ---------------------------------------------------------------------------
__global__ void __launch_bounds__(SCAN_BLK)
csr_kernel(const int* __restrict__ ei, int E, int N, int nb)
{
    __shared__ int wsum[32];
    __shared__ int sh2[128];
    __shared__ int s_boff;

    const int t    = threadIdx.x;
    const int lane = t & 31;
    const int wid  = t >> 5;
    const int b    = blockIdx.x;
    const int gtid = b * SCAN_BLK + t;
    const int gsz  = nb * SCAN_BLK;

    // ---- phase 1: histogram (int4 grid-stride) ----
    const int nquad = E >> 2;
    for (int q = gtid; q < nquad; q += gsz) {
        int4 s = ((const int4*)ei)[q];
        atomicAdd(&g_cnt[s.x], 1);
        atomicAdd(&g_cnt[s.y], 1);
        atomicAdd(&g_cnt[s.z], 1);
        atomicAdd(&g_cnt[s.w], 1);
    }
    for (int e = (nquad << 2) + gtid; e < E; e += gsz)
        atomicAdd(&g_cnt[ei[e]], 1);

    // ---- grid barrier ----
    __syncthreads();
    if (t == 0) {
        __threadfence();
        int ticket = atomicAdd(&g_bar1, 1);
        if (ticket == nb - 1) atomicExch(&g_rel1, 1);
        while (atomicAdd(&g_rel1, 0) == 0) {}
        __threadfence();
    }
    __syncthreads();

    // ---- phase 2: block-local exclusive scan of slice ----
    const int i = gtid;
    int v = (i < N) ? g_cnt[i] : 0;
    int x = v;
    #pragma unroll
    for (int off = 1; off < 32; off <<= 1) {
        int y = __shfl_up_sync(0xffffffffu, x, off);
        if (lane >= off) x += y;
    }
    if (lane == 31) wsum[wid] = x;
    __syncthreads();
    if (wid == 0) {
        int s = wsum[lane];
        #pragma unroll
        for (int off = 1; off < 32; off <<= 1) {
            int y = __shfl_up_sync(0xffffffffu, s, off);
            if (lane >= off) s += y;
        }
        wsum[lane] = s;
    }
    __syncthreads();
    const int base = (wid > 0) ? wsum[wid - 1] : 0;
    const int excl = base + x - v;

    // publish block total (release)
    if (t == SCAN_BLK - 1) {
        g_bsum[b] = base + x;
        __threadfence();
        atomicExch(&g_ready[b], 1);
    }

    // every block gathers all block totals, scans them locally
    int val = 0;
    if (t < nb) {
        while (atomicAdd(&g_ready[t], 0) == 0) {}
        __threadfence();
        val = g_bsum[t];
    }
    if (t < 128) sh2[t] = (t < nb) ? val : 0;
    __syncthreads();
    #pragma unroll
    for (int off = 1; off < 128; off <<= 1) {
        int y = (t < 128 && t >= off) ? sh2[t - off] : 0;
        __syncthreads();
        if (t < 128) sh2[t] += y;
        __syncthreads();
    }
    if (t == b) s_boff = sh2[b] - val;     // exclusive offset for this block
    __syncthreads();

    if (i < N) {
        int rp = s_boff + excl;
        g_rowptr[i] = rp;
        g_cursor[i] = rp;
    }

    // ---- reset sync state (last block out resets everything) ----
    __syncthreads();
    if (t == 0) {
        int d = atomicAdd(&g_done1, 1);
        if (d == nb - 1) {
            for (int k = 0; k < nb; k++) g_ready[k] = 0;
            g_bar1 = 0;
            g_rel1 = 0;
            g_done1 = 0;
            __threadfence();
        }
    }
}

__global__ void scatter_kernel(const int* __restrict__ ei, int E)
{
    int b = (blockIdx.x * blockDim.x + threadIdx.x) * 4;
    if (b + 3 < E) {
        int4 s = *(const int4*)&ei[b];
        int4 d = *(const int4*)&ei[E + b];
        g_sdst[atomicAdd(&g_cursor[s.x], 1)] = d.x;
        g_sdst[atomicAdd(&g_cursor[s.y], 1)] = d.y;
        g_sdst[atomicAdd(&g_cursor[s.z], 1)] = d.z;
        g_sdst[atomicAdd(&g_cursor[s.w], 1)] = d.w;
    } else {
        for (int e = b; e < E; e++) {
            int s = ei[e];
            int d = ei[E + e];
            g_sdst[atomicAdd(&g_cursor[s], 1)] = d;
        }
    }
}

// ---------------------------------------------------------------------------
// Fused softmax + aggregate: one warp per node, 8 edges in flight, index
// prefetch, interleaved K/V gathers.  Re-zeros g_cnt for next call.
// ---------------------------------------------------------------------------
__global__ void __launch_bounds__(256)
agg_kernel(float* __restrict__ out, int N)
{
    const int warp = (blockIdx.x * blockDim.x + threadIdx.x) >> 5;
    const int lane = threadIdx.x & 31;
    if (warp >= N) return;
    const int n   = warp;
    const int g   = lane >> 3;
    const int sub = lane & 7;

    const float4 q4 = *(const float4*)&g_Q[(size_t)n * HD + sub * 4];

    const int rs  = g_rowptr[n];
    const int cnt = g_cnt[n];
    const int nit = (cnt + 7) >> 3;

    float4 acc = make_float4(0.f, 0.f, 0.f, 0.f);
    float  sw  = 0.f;

    bool v0 = (g < cnt);
    bool v1 = (g + 4 < cnt);
    int  d0 = v0 ? g_sdst[rs + g] : 0;
    int  d1 = v1 ? g_sdst[rs + g + 4] : 0;

    for (int it = 0; it < nit; it++) {
        const float* kv0 = &g_KV[(size_t)d0 * 64];
        const float* kv1 = &g_KV[(size_t)d1 * 64];
        const float4 k0 = *(const float4*)&kv0[sub * 4];
        const float4 k1 = *(const float4*)&kv1[sub * 4];
        const float4 u0 = *(const float4*)&kv0[32 + sub * 4];
        const float4 u1 = *(const float4*)&kv1[32 + sub * 4];

        bool nv0 = false, nv1 = false;
        int  nd0 = 0, nd1 = 0;
        if (it + 1 < nit) {
            int jj = (it + 1) * 8 + g;
            nv0 = (jj < cnt);
            nv1 = (jj + 4 < cnt);
            nd0 = nv0 ? g_sdst[rs + jj] : 0;
            nd1 = nv1 ? g_sdst[rs + jj + 4] : 0;
        }

        float p0 = q4.x * k0.x + q4.y * k0.y + q4.z * k0.z + q4.w * k0.w;
        float p1 = q4.x * k1.x + q4.y * k1.y + q4.z * k1.z + q4.w * k1.w;
        p0 += __shfl_xor_sync(0xffffffffu, p0, 1);
        p1 += __shfl_xor_sync(0xffffffffu, p1, 1);
        p0 += __shfl_xor_sync(0xffffffffu, p0, 2);
        p1 += __shfl_xor_sync(0xffffffffu, p1, 2);
        p0 += __shfl_xor_sync(0xffffffffu, p0, 4);
        p1 += __shfl_xor_sync(0xffffffffu, p1, 4);

        float w0 = v0 ? __expf(p0 * 0.17677669529663687f) : 0.f;
        float w1 = v1 ? __expf(p1 * 0.17677669529663687f) : 0.f;
        sw += w0 + w1;

        acc.x += w0 * u0.x + w1 * u1.x;
        acc.y += w0 * u0.y + w1 * u1.y;
        acc.z += w0 * u0.z + w1 * u1.z;
        acc.w += w0 * u0.w + w1 * u1.w;

        v0 = nv0; v1 = nv1; d0 = nd0; d1 = nd1;
    }

    #pragma unroll
    for (int off = 8; off <= 16; off <<= 1) {
        acc.x += __shfl_xor_sync(0xffffffffu, acc.x, off);
        acc.y += __shfl_xor_sync(0xffffffffu, acc.y, off);
        acc.z += __shfl_xor_sync(0xffffffffu, acc.z, off);
        acc.w += __shfl_xor_sync(0xffffffffu, acc.w, off);
        sw    += __shfl_xor_sync(0xffffffffu, sw,    off);
    }

    if (lane == 0) g_cnt[n] = 0;

    if (lane < 8) {
        float inv = (sw > 0.f) ? (1.f / sw) : 0.f;
        float4 o = make_float4(acc.x * inv, acc.y * inv, acc.z * inv, acc.w * inv);
        *(float4*)&out[(size_t)n * HD + sub * 4] = o;
    }
}

// ---------------------------------------------------------------------------
// Launch: 4 kernels, fork-join across two streams.
//   csr(1,s0)  qkv(2,s1)  scatter(3,s0)  agg(4,s0, waits qkv)  <- agg profiled
// ---------------------------------------------------------------------------
extern "C" void kernel_launch(void* const* d_in, const int* in_sizes, int n_in,
                              void* d_out, int out_size)
{
    const float* X  = (const float*)d_in[0];
    const int*   ei = (const int*)d_in[1];     // int32 edge indices
    const float* Wq = (const float*)d_in[2];
    const float* Wk = (const float*)d_in[3];
    const float* Wv = (const float*)d_in[4];
    float* out = (float*)d_out;

    const int N = in_sizes[0] / IN_DIM;
    const int E = in_sizes[1] / 2;
    const int nb = (N + SCAN_BLK - 1) / SCAN_BLK;   // 98 for N=100000 (<=128)

    static cudaStream_t s1 = nullptr;
    static cudaEvent_t  evF = nullptr, evA = nullptr;
    if (!s1) {
        cudaFuncSetAttribute(qkv_mma_kernel,
                             cudaFuncAttributeMaxDynamicSharedMemorySize,
                             QKV_SMEM);
        cudaStreamCreateWithFlags(&s1, cudaStreamNonBlocking);
        cudaEventCreateWithFlags(&evF, cudaEventDisableTiming);
        cudaEventCreateWithFlags(&evA, cudaEventDisableTiming);
    }

    // Fork
    cudaEventRecord(evF, 0);
    cudaStreamWaitEvent(s1, evF, 0);

    csr_kernel<<<nb, SCAN_BLK>>>(ei, E, N, nb);                        // 1
    qkv_mma_kernel<<<(N + 127) / 128, 256, QKV_SMEM, s1>>>(X, Wq, Wk, Wv, N); // 2
    scatter_kernel<<<(E / 4 + 255) / 256, 256>>>(ei, E);               // 3

    // Join
    cudaEventRecord(evA, s1);
    cudaStreamWaitEvent(0, evA, 0);
    agg_kernel<<<(N * 32 + 255) / 256, 256>>>(out, N);                 // 4
}

// round 12
// speedup vs baseline: 1.2467x; 1.0675x over previous
#include <cuda_runtime.h>
#include <cuda_bf16.h>

// ---------------------------------------------------------------------------
// GAT-style sparse attention, CSR-fused formulation.  4 launches:
//   csr (hist+scan, grid-barrier)  [s0]   qkv (inline W-prep)  [s1]
//   scatter                        [s0]   agg (join)           [s0, profiled]
// agg: 4 nodes per warp, one 8-lane group per node (no epilogue reduction).
// edge_index arrives as int32.  Plain sm_103 target: mma.sync/ldmatrix only.
// ---------------------------------------------------------------------------

#define IN_DIM 256
#define HD 32
#define NMAX 100000
#define EMAX 1600000
#define SCAN_BLK 1024

__device__ __align__(16) float g_Q[NMAX * HD];
__device__ __align__(16) float g_KV[NMAX * 64];   // per node: K[0:32) | V[32:64)
__device__ int g_cnt[NMAX];       // zero at load; agg re-zeros for next call
__device__ int g_rowptr[NMAX];
__device__ int g_cursor[NMAX];
__device__ int g_sdst[EMAX];
__device__ int g_bsum[128];
// csr_kernel sync state (all zero at load; self-resetting each run)
__device__ int g_bar1, g_rel1, g_done1;
__device__ int g_ready[128];

// ---------------------------------------------------------------------------
// helpers
// ---------------------------------------------------------------------------
__device__ __forceinline__ unsigned smem_u32(const void* p)
{
    unsigned a;
    asm("{ .reg .u64 t; cvta.to.shared.u64 t, %1; cvt.u32.u64 %0, t; }"
        : "=r"(a) : "l"(p));
    return a;
}
__device__ __forceinline__ unsigned short bf16h(float x)
{
    return __bfloat16_as_ushort(__float2bfloat16(x));
}
__device__ __forceinline__ float bf16f(unsigned short u)
{
    return __bfloat162float(__ushort_as_bfloat16(u));
}

__device__ __forceinline__ void ldsm_x4(unsigned r[4], unsigned addr)
{
    asm volatile("ldmatrix.sync.aligned.m8n8.x4.shared.b16 {%0,%1,%2,%3}, [%4];"
                 : "=r"(r[0]), "=r"(r[1]), "=r"(r[2]), "=r"(r[3]) : "r"(addr));
}
__device__ __forceinline__ void ldsm_x2(unsigned r[2], unsigned addr)
{
    asm volatile("ldmatrix.sync.aligned.m8n8.x2.shared.b16 {%0,%1}, [%2];"
                 : "=r"(r[0]), "=r"(r[1]) : "r"(addr));
}
__device__ __forceinline__ void mma_bf16(float c[4], const unsigned a[4],
                                         const unsigned b[2])
{
    asm volatile("mma.sync.aligned.m16n8k16.row.col.f32.bf16.bf16.f32 "
                 "{%0,%1,%2,%3}, {%4,%5,%6,%7}, {%8,%9}, {%0,%1,%2,%3};"
                 : "+f"(c[0]), "+f"(c[1]), "+f"(c[2]), "+f"(c[3])
                 : "r"(a[0]), "r"(a[1]), "r"(a[2]), "r"(a[3]),
                   "r"(b[0]), "r"(b[1]));
}

// ---------------------------------------------------------------------------
// QKV GEMM via mma.sync bf16 hi/lo, software-pipelined X staging,
// per-chunk B built inline from W (hi/lo bf16 into padded smem).
// ---------------------------------------------------------------------------
#define ASTRIDE 72
#define SM_AH 0
#define SM_AL 18432
#define SM_BH 36864
#define SM_BL 50688
#define QKV_SMEM 64512

__global__ void __launch_bounds__(256, 1)
qkv_mma_kernel(const float* __restrict__ X,
               const float* __restrict__ Wq,
               const float* __restrict__ Wk,
               const float* __restrict__ Wv,
               int N)
{
    extern __shared__ char smem[];
    const unsigned sb = smem_u32(smem);
    const int tid  = threadIdx.x;
    const int wid  = tid >> 5;
    const int lane = tid & 31;
    const int n0   = blockIdx.x * 128;

    float acc[12][4];
    #pragma unroll
    for (int j = 0; j < 12; j++)
        #pragma unroll
        for (int i = 0; i < 4; i++) acc[j][i] = 0.f;

    const int a_row = (lane & 15);
    const int a_kh  = ((lane >> 4) & 1) * 8;
    const int b_row = (lane & 7);
    const int b_kh  = ((lane >> 3) & 1) * 8;

    float4 xv[8];
    #pragma unroll
    for (int ii = 0; ii < 8; ii++) {
        int q = tid + 256 * ii;
        int r = q >> 4, j4 = q & 15;
        int node = n0 + r;
        xv[ii] = (node < N)
            ? *(const float4*)&X[(size_t)node * IN_DIM + 4 * j4]
            : make_float4(0.f, 0.f, 0.f, 0.f);
    }

    for (int c = 0; c < 4; c++) {
        __syncthreads();

        // Stage A chunk c (hi/lo bf16) from prefetched registers
        #pragma unroll
        for (int ii = 0; ii < 8; ii++) {
            int q = tid + 256 * ii;
            int r = q >> 4, j4 = q & 15;
            float4 v = xv[ii];
            unsigned short hx = bf16h(v.x), hy = bf16h(v.y),
                           hz = bf16h(v.z), hw = bf16h(v.w);
            unsigned short lx = bf16h(v.x - bf16f(hx)), ly = bf16h(v.y - bf16f(hy)),
                           lz = bf16h(v.z - bf16f(hz)), lw = bf16h(v.w - bf16f(hw));
            unsigned byte = r * (ASTRIDE * 2) + 8 * j4;
            *(uint2*)(smem + SM_AH + byte) =
                make_uint2((unsigned)hx | ((unsigned)hy << 16),
                           (unsigned)hz | ((unsigned)hw << 16));
            *(uint2*)(smem + SM_AL + byte) =
                make_uint2((unsigned)lx | ((unsigned)ly << 16),
                           (unsigned)lz | ((unsigned)lw << 16));
        }

        // Build B chunk c inline from W: 3072 bf16-pairs (96 rows x 32 pairs)
        #pragma unroll
        for (int ii = 0; ii < 12; ii++) {
            int i  = tid + 256 * ii;          // 0..3071
            int n  = i % 96;
            int jp = i / 96;
            int k0 = c * 64 + 2 * jp;
            const float* Wm = (n < 32) ? Wq : (n < 64) ? Wk : Wv;
            float w0 = Wm[k0 * HD + (n & 31)];
            float w1 = Wm[(k0 + 1) * HD + (n & 31)];
            unsigned short h0 = bf16h(w0), h1 = bf16h(w1);
            unsigned short l0 = bf16h(w0 - bf16f(h0));
            unsigned short l1 = bf16h(w1 - bf16f(h1));
            unsigned byte = n * (ASTRIDE * 2) + 4 * jp;
            *(unsigned*)(smem + SM_BH + byte) = (unsigned)h0 | ((unsigned)h1 << 16);
            *(unsigned*)(smem + SM_BL + byte) = (unsigned)l0 | ((unsigned)l1 << 16);
        }
        __syncthreads();

        // Prefetch next chunk's X into registers (hidden under MMA compute)
        if (c < 3) {
            #pragma unroll
            for (int ii = 0; ii < 8; ii++) {
                int q = tid + 256 * ii;
                int r = q >> 4, j4 = q & 15;
                int node = n0 + r;
                xv[ii] = (node < N)
                    ? *(const float4*)&X[(size_t)node * IN_DIM + (c + 1) * 64 + 4 * j4]
                    : make_float4(0.f, 0.f, 0.f, 0.f);
            }
        }

        #pragma unroll
        for (int ks = 0; ks < 4; ks++) {
            unsigned ah[4], al[4];
            {
                unsigned byte = (wid * 16 + a_row) * (ASTRIDE * 2)
                              + (ks * 16 + a_kh) * 2;
                ldsm_x4(ah, sb + SM_AH + byte);
                ldsm_x4(al, sb + SM_AL + byte);
            }
            #pragma unroll
            for (int j = 0; j < 12; j++) {
                unsigned bh[2], bl[2];
                unsigned byte = (j * 8 + b_row) * (ASTRIDE * 2)
                              + (ks * 16 + b_kh) * 2;
                ldsm_x2(bh, sb + SM_BH + byte);
                ldsm_x2(bl, sb + SM_BL + byte);
                mma_bf16(acc[j], ah, bh);
                mma_bf16(acc[j], ah, bl);
                mma_bf16(acc[j], al, bh);
            }
        }
    }

    // Epilogue: Q separate; K/V interleaved per node (64-float row)
    const int g  = lane >> 2;
    const int tt = lane & 3;
    const int row_hi = n0 + wid * 16 + g;
    const int row_lo = row_hi + 8;
    #pragma unroll
    for (int j = 0; j < 12; j++) {
        int col = 8 * (j & 3) + 2 * tt;
        float* p_hi;
        float* p_lo;
        if (j < 4) {
            p_hi = &g_Q[(size_t)row_hi * HD + col];
            p_lo = &g_Q[(size_t)row_lo * HD + col];
        } else if (j < 8) {
            p_hi = &g_KV[(size_t)row_hi * 64 + col];
            p_lo = &g_KV[(size_t)row_lo * 64 + col];
        } else {
            p_hi = &g_KV[(size_t)row_hi * 64 + 32 + col];
            p_lo = &g_KV[(size_t)row_lo * 64 + 32 + col];
        }
        if (row_hi < N) *(float2*)p_hi = make_float2(acc[j][0], acc[j][1]);
        if (row_lo < N) *(float2*)p_lo = make_float2(acc[j][2], acc[j][3]);
    }
}

// ---------------------------------------------------------------------------
// CSR hist + scan in ONE kernel (grid-barrier; state self-resets).
// ---------------------------------------------------------------------------
__global__ void __launch_bounds__(SCAN_BLK)
csr_kernel(const int* __restrict__ ei, int E, int N, int nb)
{
    __shared__ int wsum[32];
    __shared__ int sh2[128];
    __shared__ int s_boff;

    const int t    = threadIdx.x;
    const int lane = t & 31;
    const int wid  = t >> 5;
    const int b    = blockIdx.x;
    const int gtid = b * SCAN_BLK + t;
    const int gsz  = nb * SCAN_BLK;

    // ---- phase 1: histogram (int4 grid-stride) ----
    const int nquad = E >> 2;
    for (int q = gtid; q < nquad; q += gsz) {
        int4 s = ((const int4*)ei)[q];
        atomicAdd(&g_cnt[s.x], 1);
        atomicAdd(&g_cnt[s.y], 1);
        atomicAdd(&g_cnt[s.z], 1);
        atomicAdd(&g_cnt[s.w], 1);
    }
    for (int e = (nquad << 2) + gtid; e < E; e += gsz)
        atomicAdd(&g_cnt[ei[e]], 1);

    // ---- grid barrier ----
    __syncthreads();
    if (t == 0) {
        __threadfence();
        int ticket = atomicAdd(&g_bar1, 1);
        if (ticket == nb - 1) atomicExch(&g_rel1, 1);
        while (atomicAdd(&g_rel1, 0) == 0) {}
        __threadfence();
    }
    __syncthreads();

    // ---- phase 2: block-local exclusive scan of slice ----
    const int i = gtid;
    int v = (i < N) ? g_cnt[i] : 0;
    int x = v;
    #pragma unroll
    for (int off = 1; off < 32; off <<= 1) {
        int y = __shfl_up_sync(0xffffffffu, x, off);
        if (lane >= off) x += y;
    }
    if (lane == 31) wsum[wid] = x;
    __syncthreads();
    if (wid == 0) {
        int s = wsum[lane];
        #pragma unroll
        for (int off = 1; off < 32; off <<= 1) {
            int y = __shfl_up_sync(0xffffffffu, s, off);
            if (lane >= off) s += y;
        }
        wsum[lane] = s;
    }
    __syncthreads();
    const int base = (wid > 0) ? wsum[wid - 1] : 0;
    const int excl = base + x - v;

    if (t == SCAN_BLK - 1) {
        g_bsum[b] = base + x;
        __threadfence();
        atomicExch(&g_ready[b], 1);
    }

    int val = 0;
    if (t < nb) {
        while (atomicAdd(&g_ready[t], 0) == 0) {}
        __threadfence();
        val = g_bsum[t];
    }
    if (t < 128) sh2[t] = (t < nb) ? val : 0;
    __syncthreads();
    #pragma unroll
    for (int off = 1; off < 128; off <<= 1) {
        int y = (t < 128 && t >= off) ? sh2[t - off] : 0;
        __syncthreads();
        if (t < 128) sh2[t] += y;
        __syncthreads();
    }
    if (t == b) s_boff = sh2[b] - val;
    __syncthreads();

    if (i < N) {
        int rp = s_boff + excl;
        g_rowptr[i] = rp;
        g_cursor[i] = rp;
    }

    __syncthreads();
    if (t == 0) {
        int d = atomicAdd(&g_done1, 1);
        if (d == nb - 1) {
            for (int k = 0; k < nb; k++) g_ready[k] = 0;
            g_bar1 = 0;
            g_rel1 = 0;
            g_done1 = 0;
            __threadfence();
        }
    }
}

__global__ void scatter_kernel(const int* __restrict__ ei, int E)
{
    int b = (blockIdx.x * blockDim.x + threadIdx.x) * 4;
    if (b + 3 < E) {
        int4 s = *(const int4*)&ei[b];
        int4 d = *(const int4*)&ei[E + b];
        g_sdst[atomicAdd(&g_cursor[s.x], 1)] = d.x;
        g_sdst[atomicAdd(&g_cursor[s.y], 1)] = d.y;
        g_sdst[atomicAdd(&g_cursor[s.z], 1)] = d.z;
        g_sdst[atomicAdd(&g_cursor[s.w], 1)] = d.w;
    } else {
        for (int e = b; e < E; e++) {
            int s = ei[e];
            int d = ei[E + e];
            g_sdst[atomicAdd(&g_cursor[s], 1)] = d;
        }
    }
}

// ---------------------------------------------------------------------------
// Fused softmax + aggregate: FOUR nodes per warp, one 8-lane group per node.
// Group-local 2-edge-unrolled loop with index prefetch; accumulator IS the
// output row (no epilogue reduction).  Re-zeros g_cnt for next call.
// ---------------------------------------------------------------------------
__global__ void __launch_bounds__(256)
agg_kernel(float* __restrict__ out, int N)
{
    const int lane = threadIdx.x & 31;
    const int warp = (blockIdx.x * blockDim.x + threadIdx.x) >> 5;
    const int grp  = lane >> 3;        // group 0..3 -> node
    const int sub  = lane & 7;         // dim quarter within node
    const int n    = warp * 4 + grp;
    const bool nvalid = (n < N);
    const int nn   = nvalid ? n : 0;

    const float4 q4 = *(const float4*)&g_Q[(size_t)nn * HD + sub * 4];
    const int rs  = g_rowptr[nn];
    const int cnt = nvalid ? g_cnt[nn] : 0;

    // uniform trip count = warp max of per-group iteration counts
    int nit = (cnt + 1) >> 1;
    nit = max(nit, __shfl_xor_sync(0xffffffffu, nit, 8));
    nit = max(nit, __shfl_xor_sync(0xffffffffu, nit, 16));

    float4 acc = make_float4(0.f, 0.f, 0.f, 0.f);
    float  sw  = 0.f;

    bool v0 = (0 < cnt);
    bool v1 = (1 < cnt);
    int  d0 = v0 ? g_sdst[rs] : 0;
    int  d1 = v1 ? g_sdst[rs + 1] : 0;

    for (int it = 0; it < nit; it++) {
        // gathers (predicated off for idle groups -> no traffic)
        float4 k0 = make_float4(0.f, 0.f, 0.f, 0.f), u0 = k0, k1 = k0, u1 = k0;
        if (v0) {
            const float* kv = &g_KV[(size_t)d0 * 64];
            k0 = *(const float4*)&kv[sub * 4];
            u0 = *(const float4*)&kv[32 + sub * 4];
        }
        if (v1) {
            const float* kv = &g_KV[(size_t)d1 * 64];
            k1 = *(const float4*)&kv[sub * 4];
            u1 = *(const float4*)&kv[32 + sub * 4];
        }

        // prefetch next pair of indices
        bool nv0 = false, nv1 = false;
        int  nd0 = 0, nd1 = 0;
        {
            int e = (it + 1) * 2;
            nv0 = (e < cnt);
            nv1 = (e + 1 < cnt);
            nd0 = nv0 ? g_sdst[rs + e] : 0;
            nd1 = nv1 ? g_sdst[rs + e + 1] : 0;
        }

        float p0 = q4.x * k0.x + q4.y * k0.y + q4.z * k0.z + q4.w * k0.w;
        float p1 = q4.x * k1.x + q4.y * k1.y + q4.z * k1.z + q4.w * k1.w;
        p0 += __shfl_xor_sync(0xffffffffu, p0, 1);
        p1 += __shfl_xor_sync(0xffffffffu, p1, 1);
        p0 += __shfl_xor_sync(0xffffffffu, p0, 2);
        p1 += __shfl_xor_sync(0xffffffffu, p1, 2);
        p0 += __shfl_xor_sync(0xffffffffu, p0, 4);
        p1 += __shfl_xor_sync(0xffffffffu, p1, 4);

        float w0 = v0 ? __expf(p0 * 0.17677669529663687f) : 0.f;
        float w1 = v1 ? __expf(p1 * 0.17677669529663687f) : 0.f;
        sw += w0 + w1;

        acc.x += w0 * u0.x + w1 * u1.x;
        acc.y += w0 * u0.y + w1 * u1.y;
        acc.z += w0 * u0.z + w1 * u1.z;
        acc.w += w0 * u0.w + w1 * u1.w;

        v0 = nv0; v1 = nv1; d0 = nd0; d1 = nd1;
    }

    if (nvalid) {
        if (sub == 0) g_cnt[n] = 0;    // reset for next call's histogram
        float inv = (sw > 0.f) ? (1.f / sw) : 0.f;
        float4 o = make_float4(acc.x * inv, acc.y * inv, acc.z * inv, acc.w * inv);
        *(float4*)&out[(size_t)n * HD + sub * 4] = o;
    }
}

// ---------------------------------------------------------------------------
// Launch: 4 kernels, fork-join across two streams.
//   csr(1,s0)  qkv(2,s1)  scatter(3,s0)  agg(4,s0, waits qkv)  <- agg profiled
// ---------------------------------------------------------------------------
extern "C" void kernel_launch(void* const* d_in, const int* in_sizes, int n_in,
                              void* d_out, int out_size)
{
    const float* X  = (const float*)d_in[0];
    const int*   ei = (const int*)d_in[1];     // int32 edge indices
    const float* Wq = (const float*)d_in[2];
    const float* Wk = (const float*)d_in[3];
    const float* Wv = (const float*)d_in[4];
    float* out = (float*)d_out;

    const int N = in_sizes[0] / IN_DIM;
    const int E = in_sizes[1] / 2;
    const int nb = (N + SCAN_BLK - 1) / SCAN_BLK;   // 98 for N=100000 (<=128)

    static cudaStream_t s1 = nullptr;
    static cudaEvent_t  evF = nullptr, evA = nullptr;
    if (!s1) {
        cudaFuncSetAttribute(qkv_mma_kernel,
                             cudaFuncAttributeMaxDynamicSharedMemorySize,
                             QKV_SMEM);
        cudaStreamCreateWithFlags(&s1, cudaStreamNonBlocking);
        cudaEventCreateWithFlags(&evF, cudaEventDisableTiming);
        cudaEventCreateWithFlags(&evA, cudaEventDisableTiming);
    }

    // Fork
    cudaEventRecord(evF, 0);
    cudaStreamWaitEvent(s1, evF, 0);

    csr_kernel<<<nb, SCAN_BLK>>>(ei, E, N, nb);                        // 1
    qkv_mma_kernel<<<(N + 127) / 128, 256, QKV_SMEM, s1>>>(X, Wq, Wk, Wv, N); // 2
    scatter_kernel<<<(E / 4 + 255) / 256, 256>>>(ei, E);               // 3

    // Join
    cudaEventRecord(evA, s1);
    cudaStreamWaitEvent(0, evA, 0);
    // 4 nodes per warp -> 8 threads per node
    agg_kernel<<<((N * 8) + 255) / 256, 256>>>(out, N);                // 4
}